// round 12
// baseline (speedup 1.0000x reference)
#include <cuda_runtime.h>
#include <cuda_bf16.h>
#include <cuda_fp8.h>
#include <cstdint>

// ============================================================================
// Problem constants — inputs and output are FLOAT32 buffers (bf16 values
// materialized as f32 by the harness; output compared as f32 of bf16 values)
// ============================================================================
static constexpr int K_DIM = 2048;
static constexpr int N_DIM = 2048;
static constexpr int M_MAX = 8192;

// amax partials layout
static constexpr int XBLK = 1536;
static constexpr int WBLK = 768;
static constexpr int QXB  = 2048;
static constexpr int QWB  = 1024;

// fp8 scratch + scalars (device globals — no allocation allowed)
__device__ __align__(128) unsigned char g_x_fp8[(size_t)M_MAX * K_DIM];  // 16 MB
__device__ __align__(128) unsigned char g_w_fp8[(size_t)N_DIM * K_DIM]; //  4 MB
__device__ float g_part[XBLK + WBLK];
__device__ float g_scale[2];
__device__ float g_scale_comb;

__device__ __forceinline__ uint32_t smem_to_u32(const void* smem_ptr) {
    uint32_t addr;
    asm("{ .reg .u64 tmp; cvta.to.shared.u64 tmp, %1; cvt.u32.u64 %0, tmp; }"
        : "=r"(addr) : "l"(smem_ptr));
    return addr;
}

#define CP_ASYNC16_OFF(dst, dimm, src, simm) \
    asm volatile("cp.async.cg.shared.global [%0+%1], [%2+%3], 16;" \
                 :: "r"(dst), "n"(dimm), "l"(src), "n"(simm) : "memory")
#define CP_ASYNC_COMMIT() asm volatile("cp.async.commit_group;" ::: "memory")
#define CP_ASYNC_WAIT1()  asm volatile("cp.async.wait_group 1;" ::: "memory")

#define LDMATRIX_X4_OFF(r0, r1, r2, r3, addr, imm) \
    asm volatile("ldmatrix.sync.aligned.m8n8.x4.shared.b16 {%0,%1,%2,%3}, [%4+%5];" \
                 : "=r"(r0), "=r"(r1), "=r"(r2), "=r"(r3) : "r"(addr), "n"(imm))

#define MMA_E4M3(c0, c1, c2, c3, a0, a1, a2, a3, b0, b1) \
    asm volatile("mma.sync.aligned.m16n8k32.row.col.f32.e4m3.e4m3.f32 " \
                 "{%0,%1,%2,%3}, {%4,%5,%6,%7}, {%8,%9}, {%0,%1,%2,%3};" \
                 : "+f"(c0), "+f"(c1), "+f"(c2), "+f"(c3) \
                 : "r"(a0), "r"(a1), "r"(a2), "r"(a3), "r"(b0), "r"(b1))

// ============================================================================
// Kernel 1: fused amax over both tensors -> per-block partials
// ============================================================================
__device__ __forceinline__ float block_reduce_max(float m) {
    #pragma unroll
    for (int o = 16; o > 0; o >>= 1)
        m = fmaxf(m, __shfl_xor_sync(0xFFFFFFFFu, m, o));
    __shared__ float smax[8];
    int wid = threadIdx.x >> 5, lid = threadIdx.x & 31;
    if (lid == 0) smax[wid] = m;
    __syncthreads();
    if (wid == 0) {
        m = (lid < (int)(blockDim.x >> 5)) ? smax[lid] : 0.0f;
        #pragma unroll
        for (int o = 4; o > 0; o >>= 1)
            m = fmaxf(m, __shfl_xor_sync(0xFFFFFFFFu, m, o));
    }
    return m;
}

__global__ void amax_both_kernel(const float* __restrict__ x, size_t nx4,
                                 const float* __restrict__ w, size_t nw4) {
    bool is_x = (blockIdx.x < XBLK);
    const float4* p = reinterpret_cast<const float4*>(is_x ? x : w);
    size_t n4   = is_x ? nx4 : nw4;
    int    bid  = is_x ? blockIdx.x : (blockIdx.x - XBLK);
    int    nblk = is_x ? XBLK : WBLK;

    float m = 0.0f;
    size_t i = (size_t)bid * blockDim.x + threadIdx.x;
    size_t stride = (size_t)nblk * blockDim.x;
    for (; i < n4; i += stride) {
        float4 v = p[i];
        m = fmaxf(m, fmaxf(fmaxf(fabsf(v.x), fabsf(v.y)),
                           fmaxf(fabsf(v.z), fabsf(v.w))));
    }
    m = block_reduce_max(m);
    if (threadIdx.x == 0) g_part[blockIdx.x] = m;
}

// ============================================================================
// Kernel 2: reduce partials -> scales
// ============================================================================
__global__ void scales_kernel() {
    int tid = threadIdx.x;   // 256 threads
    float mx = 0.0f, mw = 0.0f;
    for (int i = tid; i < XBLK; i += 256) mx = fmaxf(mx, g_part[i]);
    for (int i = XBLK + tid; i < XBLK + WBLK; i += 256) mw = fmaxf(mw, g_part[i]);
    #pragma unroll
    for (int o = 16; o > 0; o >>= 1) {
        mx = fmaxf(mx, __shfl_xor_sync(0xFFFFFFFFu, mx, o));
        mw = fmaxf(mw, __shfl_xor_sync(0xFFFFFFFFu, mw, o));
    }
    __shared__ float sx8[8], sw8[8];
    int wid = tid >> 5, lid = tid & 31;
    if (lid == 0) { sx8[wid] = mx; sw8[wid] = mw; }
    __syncthreads();
    if (tid == 0) {
        float ax = 0.0f, aw = 0.0f;
        #pragma unroll
        for (int i = 0; i < 8; i++) {
            ax = fmaxf(ax, sx8[i]);
            aw = fmaxf(aw, sw8[i]);
        }
        float sxv = fmaxf(__fdiv_rn(ax, 448.0f), 1e-12f);
        float swv = fmaxf(__fdiv_rn(aw, 448.0f), 1e-12f);
        g_scale[0] = sxv;
        g_scale[1] = swv;
        g_scale_comb = sxv * swv;
    }
}

// ============================================================================
// Kernel 3: fused quantize f32 -> e4m3 for both tensors (RNE satfinite)
// ============================================================================
__global__ void quant_both_kernel(const float* __restrict__ x, unsigned char* __restrict__ xq, size_t nx8,
                                  const float* __restrict__ w, unsigned char* __restrict__ wq, size_t nw8) {
    bool is_x = (blockIdx.x < QXB);
    const float4* p = reinterpret_cast<const float4*>(is_x ? x : w);
    uint2* q  = reinterpret_cast<uint2*>(is_x ? xq : wq);
    size_t n8 = is_x ? nx8 : nw8;
    int bid   = is_x ? blockIdx.x : (blockIdx.x - QXB);
    int nblk  = is_x ? QXB : QWB;
    float s   = g_scale[is_x ? 0 : 1];

    size_t i = (size_t)bid * blockDim.x + threadIdx.x;
    size_t stride = (size_t)nblk * blockDim.x;
    for (; i < n8; i += stride) {
        float4 v0 = p[2 * i];
        float4 v1 = p[2 * i + 1];
        float2 f0 = make_float2(__fdiv_rn(v0.x, s), __fdiv_rn(v0.y, s));
        float2 f1 = make_float2(__fdiv_rn(v0.z, s), __fdiv_rn(v0.w, s));
        float2 f2 = make_float2(__fdiv_rn(v1.x, s), __fdiv_rn(v1.y, s));
        float2 f3 = make_float2(__fdiv_rn(v1.z, s), __fdiv_rn(v1.w, s));
        uint32_t b0 = __nv_cvt_float2_to_fp8x2(f0, __NV_SATFINITE, __NV_E4M3);
        uint32_t b1 = __nv_cvt_float2_to_fp8x2(f1, __NV_SATFINITE, __NV_E4M3);
        uint32_t b2 = __nv_cvt_float2_to_fp8x2(f2, __NV_SATFINITE, __NV_E4M3);
        uint32_t b3 = __nv_cvt_float2_to_fp8x2(f3, __NV_SATFINITE, __NV_E4M3);
        uint2 r;
        r.x = (b0 & 0xFFFFu) | (b1 << 16);
        r.y = (b2 & 0xFFFFu) | (b3 << 16);
        q[i] = r;
    }
}

// ============================================================================
// Kernel 4: FP8 GEMM via mma.sync.m16n8k32 e4m3
//   CTA 128x128, 512 threads, warp grid 4(M) x 4(N), warp tile 32x32
//   (8 warps/SMSP at 2 CTA/SM; fp8 halves LDSM crossbar traffic vs f16).
//   BK=128 bytes, 3-stage cp.async, one barrier/iter, immediate offsets.
// ============================================================================
static constexpr int BM = 128, BN = 128, BK = 128;
static constexpr int STAGES = 3;
static constexpr int PITCH = 144;                   // 128 data + 16 pad
static constexpr int TILE_A = BM * PITCH;           // 18432 bytes
static constexpr int STAGE_B = 2 * TILE_A;          // 36864 bytes per stage
static constexpr int GEMM_SMEM = STAGES * STAGE_B;  // 110592 bytes
static constexpr int KITERS = K_DIM / BK;           // 16
static constexpr int MF_STEP = 16 * PITCH;          // 2304
static constexpr int ROWB = K_DIM;                  // gmem row pitch bytes (fp8)

// one k32 step for a 32x32 warp tile: 2 A-LDSM + 2 B-LDSM + 8 MMA
template <int KS>
__device__ __forceinline__ void kstep(uint32_t aB, uint32_t bB, float (&c)[2][4][4]) {
    uint32_t a[2][4];
    LDMATRIX_X4_OFF(a[0][0], a[0][1], a[0][2], a[0][3], aB, 0 * MF_STEP + KS * 32);
    LDMATRIX_X4_OFF(a[1][0], a[1][1], a[1][2], a[1][3], aB, 1 * MF_STEP + KS * 32);

    uint32_t b[4][2];
    {
        uint32_t r0, r1, r2, r3;
        LDMATRIX_X4_OFF(r0, r1, r2, r3, bB, 0 * MF_STEP + KS * 32);
        b[0][0] = r0; b[0][1] = r2;
        b[1][0] = r1; b[1][1] = r3;
        LDMATRIX_X4_OFF(r0, r1, r2, r3, bB, 1 * MF_STEP + KS * 32);
        b[2][0] = r0; b[2][1] = r2;
        b[3][0] = r1; b[3][1] = r3;
    }

    #pragma unroll
    for (int mf = 0; mf < 2; mf++)
        #pragma unroll
        for (int nf = 0; nf < 4; nf++)
            MMA_E4M3(c[mf][nf][0], c[mf][nf][1], c[mf][nf][2], c[mf][nf][3],
                     a[mf][0], a[mf][1], a[mf][2], a[mf][3],
                     b[nf][0], b[nf][1]);
}

// 4 cp.async chunks per thread per stage (A: 2, B: 2); offsets immediate
__device__ __forceinline__ void load_stage(uint32_t d0, const uint8_t* sA, const uint8_t* sB) {
    CP_ASYNC16_OFF(d0, 0,                   sA, 0);
    CP_ASYNC16_OFF(d0, 64 * PITCH,          sA, 64 * ROWB);
    CP_ASYNC16_OFF(d0, TILE_A,              sB, 0);
    CP_ASYNC16_OFF(d0, TILE_A + 64 * PITCH, sB, 64 * ROWB);
}

__global__ void __launch_bounds__(512, 2) gemm_kernel(
    const uint8_t* __restrict__ Aq, const uint8_t* __restrict__ Bq,
    float* __restrict__ out)
{
    extern __shared__ char smem[];
    uint32_t sbase = smem_to_u32(smem);
    int tid  = threadIdx.x;
    int lane = tid & 31;
    int wid  = tid >> 5;            // 0..15
    int warp_m = wid & 3;           // 0..3 -> 32 rows each
    int warp_n = wid >> 2;          // 0..3 -> 32 cols each
    int m0 = blockIdx.x * BM;
    int n0 = blockIdx.y * BN;

    // per-thread load bases: row (tid>>3) in 0..63 (+64 via immediate), chunk (tid&7)
    int lrow = tid >> 3;
    int lch  = (tid & 7) * 16;
    const uint8_t* srcA = Aq + (size_t)(m0 + lrow) * ROWB + lch;
    const uint8_t* srcB = Bq + (size_t)(n0 + lrow) * ROWB + lch;
    uint32_t dof0 = (uint32_t)lrow * PITCH + lch;

    float c[2][4][4];
    #pragma unroll
    for (int mf = 0; mf < 2; mf++)
        #pragma unroll
        for (int nf = 0; nf < 4; nf++)
            #pragma unroll
            for (int e = 0; e < 4; e++) c[mf][nf][e] = 0.0f;

    // prologue: stages 0,1
    load_stage(sbase + 0 * STAGE_B + dof0, srcA, srcB); srcA += BK; srcB += BK;
    CP_ASYNC_COMMIT();
    load_stage(sbase + 1 * STAGE_B + dof0, srcA, srcB); srcA += BK; srcB += BK;
    CP_ASYNC_COMMIT();

    // hoisted LDSM row bases
    int frow = lane & 15;
    int fch  = lane >> 4;
    uint32_t arow = (uint32_t)(warp_m * 32 + frow) * PITCH + fch * 16;
    uint32_t brow = TILE_A + (uint32_t)(warp_n * 32 + frow) * PITCH + fch * 16;

    uint32_t pf_off = 2 * STAGE_B;
    uint32_t cs_off = 0;

    for (int ki = 0; ki < KITERS; ki++) {
        CP_ASYNC_WAIT1();
        __syncthreads();   // stage (ki-1)%3 fully consumed by all warps

        if (ki + 2 < KITERS) {
            load_stage(sbase + pf_off + dof0, srcA, srcB);
            srcA += BK; srcB += BK;
        }
        CP_ASYNC_COMMIT();
        pf_off += STAGE_B; if (pf_off == GEMM_SMEM) pf_off = 0;

        uint32_t aB = sbase + cs_off + arow;
        uint32_t bB = sbase + cs_off + brow;
        cs_off += STAGE_B; if (cs_off == GEMM_SMEM) cs_off = 0;

        kstep<0>(aB, bB, c);   // k bytes 0-31
        kstep<1>(aB, bB, c);   // 32-63
        kstep<2>(aB, bB, c);   // 64-95
        kstep<3>(aB, bB, c);   // 96-127
    }

    // epilogue: scale, round to bf16 (reference casts to bf16), store as f32
    float sc = g_scale_comb;
    int r  = lane >> 2;
    int cq = (lane & 3) * 2;
    #pragma unroll
    for (int mf = 0; mf < 2; mf++) {
        #pragma unroll
        for (int nf = 0; nf < 4; nf++) {
            int gm = m0 + warp_m * 32 + mf * 16 + r;
            int gn = n0 + warp_n * 32 + nf * 8 + cq;
            float2 e0, e1;
            e0.x = __bfloat162float(__float2bfloat16_rn(c[mf][nf][0] * sc));
            e0.y = __bfloat162float(__float2bfloat16_rn(c[mf][nf][1] * sc));
            e1.x = __bfloat162float(__float2bfloat16_rn(c[mf][nf][2] * sc));
            e1.y = __bfloat162float(__float2bfloat16_rn(c[mf][nf][3] * sc));
            *reinterpret_cast<float2*>(out + (size_t)gm * N_DIM + gn) = e0;
            *reinterpret_cast<float2*>(out + (size_t)(gm + 8) * N_DIM + gn) = e1;
        }
    }
}

// ============================================================================
// Host launcher — exactly 4 launches (amax, scales, quant, gemm)
// ============================================================================
extern "C" void kernel_launch(void* const* d_in, const int* in_sizes, int n_in,
                              void* d_out, int out_size) {
    int ix = 0, iw = 1;
    if (n_in >= 2 && in_sizes[1] > in_sizes[0]) { ix = 1; iw = 0; }
    const float* x = (const float*)d_in[ix];
    const float* w = (const float*)d_in[iw];
    float* out = (float*)d_out;

    size_t nx = (size_t)in_sizes[ix];   // 16,777,216
    size_t nw = (size_t)in_sizes[iw];   //  4,194,304
    int M = (int)(nx / K_DIM);          // 8192

    void *xq = nullptr, *wq = nullptr;
    cudaGetSymbolAddress(&xq, g_x_fp8);
    cudaGetSymbolAddress(&wq, g_w_fp8);

    amax_both_kernel<<<XBLK + WBLK, 256>>>(x, nx / 4, w, nw / 4);
    scales_kernel<<<1, 256>>>();
    quant_both_kernel<<<QXB + QWB, 256>>>(x, (unsigned char*)xq, nx / 8,
                                          w, (unsigned char*)wq, nw / 8);

    cudaFuncSetAttribute(gemm_kernel, cudaFuncAttributeMaxDynamicSharedMemorySize, GEMM_SMEM);
    dim3 grid(M / BM, N_DIM / BN);
    gemm_kernel<<<grid, 512, GEMM_SMEM>>>((const uint8_t*)xq, (const uint8_t*)wq, out);
}

// round 13
// speedup vs baseline: 1.3797x; 1.3797x over previous
#include <cuda_runtime.h>
#include <cuda_bf16.h>
#include <cuda_fp8.h>
#include <cstdint>

// ============================================================================
// Problem constants — inputs and output are FLOAT32 buffers (bf16 values
// materialized as f32 by the harness; output compared as f32 of bf16 values)
// ============================================================================
static constexpr int K_DIM = 2048;
static constexpr int N_DIM = 2048;
static constexpr int M_MAX = 8192;

static constexpr int XBLK = 1536;
static constexpr int WBLK = 768;
static constexpr int QXB  = 2048;
static constexpr int QWB  = 1024;

// fp8 scratch + scalars (device globals — no allocation allowed)
__device__ __align__(128) unsigned char g_x_fp8[(size_t)M_MAX * K_DIM];  // 16 MB
__device__ __align__(128) unsigned char g_w_fp8[(size_t)N_DIM * K_DIM]; //  4 MB
__device__ float g_part[XBLK + WBLK];
__device__ float g_scale_comb;

__device__ __forceinline__ uint32_t smem_to_u32(const void* smem_ptr) {
    uint32_t addr;
    asm("{ .reg .u64 tmp; cvta.to.shared.u64 tmp, %1; cvt.u32.u64 %0, tmp; }"
        : "=r"(addr) : "l"(smem_ptr));
    return addr;
}

#define CP_ASYNC16_OFF(dst, dimm, src, simm) \
    asm volatile("cp.async.cg.shared.global [%0+%1], [%2+%3], 16;" \
                 :: "r"(dst), "n"(dimm), "l"(src), "n"(simm) : "memory")
#define CP_ASYNC_COMMIT() asm volatile("cp.async.commit_group;" ::: "memory")
#define CP_ASYNC_WAIT1()  asm volatile("cp.async.wait_group 1;" ::: "memory")

#define LDMATRIX_X4_OFF(r0, r1, r2, r3, addr, imm) \
    asm volatile("ldmatrix.sync.aligned.m8n8.x4.shared.b16 {%0,%1,%2,%3}, [%4+%5];" \
                 : "=r"(r0), "=r"(r1), "=r"(r2), "=r"(r3) : "r"(addr), "n"(imm))

#define MMA_E4M3(c0, c1, c2, c3, a0, a1, a2, a3, b0, b1) \
    asm volatile("mma.sync.aligned.m16n8k32.row.col.f32.e4m3.e4m3.f32 " \
                 "{%0,%1,%2,%3}, {%4,%5,%6,%7}, {%8,%9}, {%0,%1,%2,%3};" \
                 : "+f"(c0), "+f"(c1), "+f"(c2), "+f"(c3) \
                 : "r"(a0), "r"(a1), "r"(a2), "r"(a3), "r"(b0), "r"(b1))

// ============================================================================
// Kernel 1: fused amax over both tensors -> per-block partials
// ============================================================================
__device__ __forceinline__ float block_reduce_max(float m) {
    #pragma unroll
    for (int o = 16; o > 0; o >>= 1)
        m = fmaxf(m, __shfl_xor_sync(0xFFFFFFFFu, m, o));
    __shared__ float smax[8];
    int wid = threadIdx.x >> 5, lid = threadIdx.x & 31;
    if (lid == 0) smax[wid] = m;
    __syncthreads();
    if (wid == 0) {
        m = (lid < (int)(blockDim.x >> 5)) ? smax[lid] : 0.0f;
        #pragma unroll
        for (int o = 4; o > 0; o >>= 1)
            m = fmaxf(m, __shfl_xor_sync(0xFFFFFFFFu, m, o));
    }
    return m;
}

__global__ void amax_both_kernel(const float* __restrict__ x, size_t nx4,
                                 const float* __restrict__ w, size_t nw4) {
    bool is_x = (blockIdx.x < XBLK);
    const float4* p = reinterpret_cast<const float4*>(is_x ? x : w);
    size_t n4   = is_x ? nx4 : nw4;
    int    bid  = is_x ? blockIdx.x : (blockIdx.x - XBLK);
    int    nblk = is_x ? XBLK : WBLK;

    float m = 0.0f;
    size_t i = (size_t)bid * blockDim.x + threadIdx.x;
    size_t stride = (size_t)nblk * blockDim.x;
    for (; i < n4; i += stride) {
        float4 v = p[i];
        m = fmaxf(m, fmaxf(fmaxf(fabsf(v.x), fabsf(v.y)),
                           fmaxf(fabsf(v.z), fabsf(v.w))));
    }
    m = block_reduce_max(m);
    if (threadIdx.x == 0) g_part[blockIdx.x] = m;
}

// ============================================================================
// Kernel 2: quantize f32 -> e4m3 (RNE satfinite); each block first reduces
// the partial maxes itself (scales kernel folded in — one less launch).
// ============================================================================
__global__ void quant_both_kernel(const float* __restrict__ x, unsigned char* __restrict__ xq, size_t nx8,
                                  const float* __restrict__ w, unsigned char* __restrict__ wq, size_t nw8) {
    // --- fold-in: reduce g_part -> scales (every block, deterministic) ---
    __shared__ float sred[8];
    __shared__ float s_scales[2];
    {
        int tid = threadIdx.x;
        float mx = 0.0f, mw = 0.0f;
        for (int i = tid; i < XBLK; i += 256) mx = fmaxf(mx, g_part[i]);
        for (int i = XBLK + tid; i < XBLK + WBLK; i += 256) mw = fmaxf(mw, g_part[i]);
        #pragma unroll
        for (int o = 16; o > 0; o >>= 1) {
            mx = fmaxf(mx, __shfl_xor_sync(0xFFFFFFFFu, mx, o));
            mw = fmaxf(mw, __shfl_xor_sync(0xFFFFFFFFu, mw, o));
        }
        int wid = tid >> 5, lid = tid & 31;
        if (lid == 0) sred[wid] = mx;
        __syncthreads();
        if (wid == 0) {
            float a = (lid < 8) ? sred[lid] : 0.0f;
            #pragma unroll
            for (int o = 4; o > 0; o >>= 1) a = fmaxf(a, __shfl_xor_sync(0xFFFFFFFFu, a, o));
            if (lid == 0) s_scales[0] = fmaxf(__fdiv_rn(a, 448.0f), 1e-12f);
        }
        __syncthreads();
        if (lid == 0) sred[wid] = mw;
        __syncthreads();
        if (wid == 0) {
            float a = (lid < 8) ? sred[lid] : 0.0f;
            #pragma unroll
            for (int o = 4; o > 0; o >>= 1) a = fmaxf(a, __shfl_xor_sync(0xFFFFFFFFu, a, o));
            if (lid == 0) {
                s_scales[1] = fmaxf(__fdiv_rn(a, 448.0f), 1e-12f);
                if (blockIdx.x == 0)
                    g_scale_comb = s_scales[0] * s_scales[1];
            }
        }
        __syncthreads();
    }

    bool is_x = (blockIdx.x < QXB);
    const float4* p = reinterpret_cast<const float4*>(is_x ? x : w);
    uint2* q  = reinterpret_cast<uint2*>(is_x ? xq : wq);
    size_t n8 = is_x ? nx8 : nw8;
    int bid   = is_x ? blockIdx.x : (blockIdx.x - QXB);
    int nblk  = is_x ? QXB : QWB;
    float s   = s_scales[is_x ? 0 : 1];

    size_t i = (size_t)bid * blockDim.x + threadIdx.x;
    size_t stride = (size_t)nblk * blockDim.x;
    for (; i < n8; i += stride) {
        float4 v0 = p[2 * i];
        float4 v1 = p[2 * i + 1];
        float2 f0 = make_float2(__fdiv_rn(v0.x, s), __fdiv_rn(v0.y, s));
        float2 f1 = make_float2(__fdiv_rn(v0.z, s), __fdiv_rn(v0.w, s));
        float2 f2 = make_float2(__fdiv_rn(v1.x, s), __fdiv_rn(v1.y, s));
        float2 f3 = make_float2(__fdiv_rn(v1.z, s), __fdiv_rn(v1.w, s));
        uint32_t b0 = __nv_cvt_float2_to_fp8x2(f0, __NV_SATFINITE, __NV_E4M3);
        uint32_t b1 = __nv_cvt_float2_to_fp8x2(f1, __NV_SATFINITE, __NV_E4M3);
        uint32_t b2 = __nv_cvt_float2_to_fp8x2(f2, __NV_SATFINITE, __NV_E4M3);
        uint32_t b3 = __nv_cvt_float2_to_fp8x2(f3, __NV_SATFINITE, __NV_E4M3);
        uint2 r;
        r.x = (b0 & 0xFFFFu) | (b1 << 16);
        r.y = (b2 & 0xFFFFu) | (b3 << 16);
        q[i] = r;
    }
}

// ============================================================================
// Kernel 3: FP8 GEMM via mma.sync.m16n8k32 e4m3 (R9 config + fragment
// double-buffering). CTA 128x128, 256 thr, warp grid 2(M)x4(N) = 64x32 tiles,
// BK=128 bytes, 3-stage cp.async, one barrier/iter, immediate offsets.
// ============================================================================
static constexpr int BM = 128, BN = 128, BK = 128;
static constexpr int STAGES = 3;
static constexpr int PITCH = 144;                   // 128 data + 16 pad
static constexpr int TILE_A = BM * PITCH;           // 18432 bytes
static constexpr int STAGE_B = 2 * TILE_A;          // 36864 bytes per stage
static constexpr int GEMM_SMEM = STAGES * STAGE_B;  // 110592 bytes
static constexpr int KITERS = K_DIM / BK;           // 16
static constexpr int MF_STEP = 16 * PITCH;          // 2304

struct Frag {
    uint32_t a[4][4];
    uint32_t b[4][2];
};

template <int KS>
__device__ __forceinline__ void load_frag(uint32_t aB, uint32_t bB, Frag& f) {
    LDMATRIX_X4_OFF(f.a[0][0], f.a[0][1], f.a[0][2], f.a[0][3], aB, 0 * MF_STEP + KS * 32);
    LDMATRIX_X4_OFF(f.a[1][0], f.a[1][1], f.a[1][2], f.a[1][3], aB, 1 * MF_STEP + KS * 32);
    LDMATRIX_X4_OFF(f.a[2][0], f.a[2][1], f.a[2][2], f.a[2][3], aB, 2 * MF_STEP + KS * 32);
    LDMATRIX_X4_OFF(f.a[3][0], f.a[3][1], f.a[3][2], f.a[3][3], aB, 3 * MF_STEP + KS * 32);
    uint32_t r0, r1, r2, r3;
    LDMATRIX_X4_OFF(r0, r1, r2, r3, bB, 0 * MF_STEP + KS * 32);
    f.b[0][0] = r0; f.b[0][1] = r2;
    f.b[1][0] = r1; f.b[1][1] = r3;
    LDMATRIX_X4_OFF(r0, r1, r2, r3, bB, 1 * MF_STEP + KS * 32);
    f.b[2][0] = r0; f.b[2][1] = r2;
    f.b[3][0] = r1; f.b[3][1] = r3;
}

__device__ __forceinline__ void mma_frag(const Frag& f, float (&c)[4][4][4]) {
    #pragma unroll
    for (int mf = 0; mf < 4; mf++)
        #pragma unroll
        for (int nf = 0; nf < 4; nf++)
            MMA_E4M3(c[mf][nf][0], c[mf][nf][1], c[mf][nf][2], c[mf][nf][3],
                     f.a[mf][0], f.a[mf][1], f.a[mf][2], f.a[mf][3],
                     f.b[nf][0], f.b[nf][1]);
}

// 8 cp.async chunks per thread per stage; offsets immediate
__device__ __forceinline__ void load_stage(uint32_t d0, const uint8_t* sA, const uint8_t* sB) {
    CP_ASYNC16_OFF(d0, 0 * 4608,          sA, 0 * 32 * K_DIM);
    CP_ASYNC16_OFF(d0, 1 * 4608,          sA, 1 * 32 * K_DIM);
    CP_ASYNC16_OFF(d0, 2 * 4608,          sA, 2 * 32 * K_DIM);
    CP_ASYNC16_OFF(d0, 3 * 4608,          sA, 3 * 32 * K_DIM);
    CP_ASYNC16_OFF(d0, TILE_A + 0 * 4608, sB, 0 * 32 * K_DIM);
    CP_ASYNC16_OFF(d0, TILE_A + 1 * 4608, sB, 1 * 32 * K_DIM);
    CP_ASYNC16_OFF(d0, TILE_A + 2 * 4608, sB, 2 * 32 * K_DIM);
    CP_ASYNC16_OFF(d0, TILE_A + 3 * 4608, sB, 3 * 32 * K_DIM);
}

__global__ void __launch_bounds__(256, 2) gemm_kernel(
    const uint8_t* __restrict__ Aq, const uint8_t* __restrict__ Bq,
    float* __restrict__ out)
{
    extern __shared__ char smem[];
    uint32_t sbase = smem_to_u32(smem);
    int tid  = threadIdx.x;
    int lane = tid & 31;
    int wid  = tid >> 5;
    int warp_m = wid & 1;
    int warp_n = wid >> 1;
    int m0 = blockIdx.x * BM;
    int n0 = blockIdx.y * BN;

    int lrow = tid >> 3;
    int lch  = (tid & 7) * 16;
    const uint8_t* srcA = Aq + (size_t)(m0 + lrow) * K_DIM + lch;
    const uint8_t* srcB = Bq + (size_t)(n0 + lrow) * K_DIM + lch;
    uint32_t dof0 = (uint32_t)lrow * PITCH + lch;

    float c[4][4][4];
    #pragma unroll
    for (int mf = 0; mf < 4; mf++)
        #pragma unroll
        for (int nf = 0; nf < 4; nf++)
            #pragma unroll
            for (int e = 0; e < 4; e++) c[mf][nf][e] = 0.0f;

    load_stage(sbase + 0 * STAGE_B + dof0, srcA, srcB); srcA += BK; srcB += BK;
    CP_ASYNC_COMMIT();
    load_stage(sbase + 1 * STAGE_B + dof0, srcA, srcB); srcA += BK; srcB += BK;
    CP_ASYNC_COMMIT();

    int frow = lane & 15;
    int fch  = lane >> 4;
    uint32_t arow = (uint32_t)(warp_m * 64 + frow) * PITCH + fch * 16;
    uint32_t brow = TILE_A + (uint32_t)(warp_n * 32 + frow) * PITCH + fch * 16;

    uint32_t pf_off = 2 * STAGE_B;
    uint32_t cs_off = 0;

    for (int ki = 0; ki < KITERS; ki++) {
        CP_ASYNC_WAIT1();
        __syncthreads();

        if (ki + 2 < KITERS) {
            load_stage(sbase + pf_off + dof0, srcA, srcB);
            srcA += BK; srcB += BK;
        }
        CP_ASYNC_COMMIT();
        pf_off += STAGE_B; if (pf_off == GEMM_SMEM) pf_off = 0;

        uint32_t aB = sbase + cs_off + arow;
        uint32_t bB = sbase + cs_off + brow;
        cs_off += STAGE_B; if (cs_off == GEMM_SMEM) cs_off = 0;

        // fragment double-buffer: load<ks+1> overlaps mma<ks>
        Frag f0, f1;
        load_frag<0>(aB, bB, f0);
        load_frag<1>(aB, bB, f1);
        mma_frag(f0, c);
        load_frag<2>(aB, bB, f0);
        mma_frag(f1, c);
        load_frag<3>(aB, bB, f1);
        mma_frag(f0, c);
        mma_frag(f1, c);
    }

    // epilogue: scale, round to bf16 (reference casts to bf16), store as f32
    float sc = g_scale_comb;
    int r  = lane >> 2;
    int cq = (lane & 3) * 2;
    #pragma unroll
    for (int mf = 0; mf < 4; mf++) {
        #pragma unroll
        for (int nf = 0; nf < 4; nf++) {
            int gm = m0 + warp_m * 64 + mf * 16 + r;
            int gn = n0 + warp_n * 32 + nf * 8 + cq;
            float2 e0, e1;
            e0.x = __bfloat162float(__float2bfloat16_rn(c[mf][nf][0] * sc));
            e0.y = __bfloat162float(__float2bfloat16_rn(c[mf][nf][1] * sc));
            e1.x = __bfloat162float(__float2bfloat16_rn(c[mf][nf][2] * sc));
            e1.y = __bfloat162float(__float2bfloat16_rn(c[mf][nf][3] * sc));
            *reinterpret_cast<float2*>(out + (size_t)gm * N_DIM + gn) = e0;
            *reinterpret_cast<float2*>(out + (size_t)(gm + 8) * N_DIM + gn) = e1;
        }
    }
}

// ============================================================================
// Host launcher — exactly 3 launches (amax, quant+scales, gemm)
// ============================================================================
extern "C" void kernel_launch(void* const* d_in, const int* in_sizes, int n_in,
                              void* d_out, int out_size) {
    int ix = 0, iw = 1;
    if (n_in >= 2 && in_sizes[1] > in_sizes[0]) { ix = 1; iw = 0; }
    const float* x = (const float*)d_in[ix];
    const float* w = (const float*)d_in[iw];
    float* out = (float*)d_out;

    size_t nx = (size_t)in_sizes[ix];   // 16,777,216
    size_t nw = (size_t)in_sizes[iw];   //  4,194,304
    int M = (int)(nx / K_DIM);          // 8192

    void *xq = nullptr, *wq = nullptr;
    cudaGetSymbolAddress(&xq, g_x_fp8);
    cudaGetSymbolAddress(&wq, g_w_fp8);

    amax_both_kernel<<<XBLK + WBLK, 256>>>(x, nx / 4, w, nw / 4);
    quant_both_kernel<<<QXB + QWB, 256>>>(x, (unsigned char*)xq, nx / 8,
                                          w, (unsigned char*)wq, nw / 8);

    cudaFuncSetAttribute(gemm_kernel, cudaFuncAttributeMaxDynamicSharedMemorySize, GEMM_SMEM);
    dim3 grid(M / BM, N_DIM / BN);
    gemm_kernel<<<grid, 256, GEMM_SMEM>>>((const uint8_t*)xq, (const uint8_t*)wq, out);
}

// round 14
// speedup vs baseline: 1.4018x; 1.0160x over previous
#include <cuda_runtime.h>
#include <cuda_bf16.h>
#include <cuda_fp8.h>
#include <cstdint>

// ============================================================================
// Problem constants — inputs and output are FLOAT32 buffers (bf16 values
// materialized as f32 by the harness; output compared as f32 of bf16 values)
// ============================================================================
static constexpr int K_DIM = 2048;
static constexpr int N_DIM = 2048;
static constexpr int M_MAX = 8192;

// amax: exact-shape, 8 float4 per thread, no loop
static constexpr int XBLK = 2048;   // x: 4,194,304 float4 / (2048*256) = 8
static constexpr int WBLK = 512;    // w: 1,048,576 float4 / (512*256)  = 8
// quant: 4 iterations of 8 elements per thread
static constexpr int QXB  = 2048;   // x: 2,097,152 chunks / (2048*256) = 4
static constexpr int QWB  = 512;    // w:   524,288 chunks / (512*256)  = 4

// fp8 scratch + scalars (device globals — no allocation allowed)
__device__ __align__(128) unsigned char g_x_fp8[(size_t)M_MAX * K_DIM];  // 16 MB
__device__ __align__(128) unsigned char g_w_fp8[(size_t)N_DIM * K_DIM]; //  4 MB
__device__ float g_part[XBLK + WBLK];
__device__ float g_scale_comb;

__device__ __forceinline__ uint32_t smem_to_u32(const void* smem_ptr) {
    uint32_t addr;
    asm("{ .reg .u64 tmp; cvta.to.shared.u64 tmp, %1; cvt.u32.u64 %0, tmp; }"
        : "=r"(addr) : "l"(smem_ptr));
    return addr;
}

#define CP_ASYNC16_OFF(dst, dimm, src, simm) \
    asm volatile("cp.async.cg.shared.global [%0+%1], [%2+%3], 16;" \
                 :: "r"(dst), "n"(dimm), "l"(src), "n"(simm) : "memory")
#define CP_ASYNC_COMMIT() asm volatile("cp.async.commit_group;" ::: "memory")
#define CP_ASYNC_WAIT1()  asm volatile("cp.async.wait_group 1;" ::: "memory")

#define LDMATRIX_X4_OFF(r0, r1, r2, r3, addr, imm) \
    asm volatile("ldmatrix.sync.aligned.m8n8.x4.shared.b16 {%0,%1,%2,%3}, [%4+%5];" \
                 : "=r"(r0), "=r"(r1), "=r"(r2), "=r"(r3) : "r"(addr), "n"(imm))

#define MMA_E4M3(c0, c1, c2, c3, a0, a1, a2, a3, b0, b1) \
    asm volatile("mma.sync.aligned.m16n8k32.row.col.f32.e4m3.e4m3.f32 " \
                 "{%0,%1,%2,%3}, {%4,%5,%6,%7}, {%8,%9}, {%0,%1,%2,%3};" \
                 : "+f"(c0), "+f"(c1), "+f"(c2), "+f"(c3) \
                 : "r"(a0), "r"(a1), "r"(a2), "r"(a3), "r"(b0), "r"(b1))

// ============================================================================
// Kernel 1: amax -> per-block partials. Exact shape: 8 independent float4
// loads per thread (MLP=8), 8 independent max chains, no loop.
// ============================================================================
__global__ void amax_both_kernel(const float* __restrict__ x,
                                 const float* __restrict__ w) {
    bool is_x = (blockIdx.x < XBLK);
    const float4* p = reinterpret_cast<const float4*>(is_x ? x : w);
    int bid = is_x ? blockIdx.x : (blockIdx.x - XBLK);

    // block covers 8 * 256 float4, thread t takes [base + j*256 + t]
    size_t base = (size_t)bid * (8 * 256) + threadIdx.x;
    float4 v[8];
    #pragma unroll
    for (int j = 0; j < 8; j++) v[j] = p[base + (size_t)j * 256];

    float m[8];
    #pragma unroll
    for (int j = 0; j < 8; j++)
        m[j] = fmaxf(fmaxf(fabsf(v[j].x), fabsf(v[j].y)),
                     fmaxf(fabsf(v[j].z), fabsf(v[j].w)));
    float mm = fmaxf(fmaxf(fmaxf(m[0], m[1]), fmaxf(m[2], m[3])),
                     fmaxf(fmaxf(m[4], m[5]), fmaxf(m[6], m[7])));

    #pragma unroll
    for (int o = 16; o > 0; o >>= 1)
        mm = fmaxf(mm, __shfl_xor_sync(0xFFFFFFFFu, mm, o));
    __shared__ float smax[8];
    int wid = threadIdx.x >> 5, lid = threadIdx.x & 31;
    if (lid == 0) smax[wid] = mm;
    __syncthreads();
    if (wid == 0) {
        mm = (lid < 8) ? smax[lid] : 0.0f;
        #pragma unroll
        for (int o = 4; o > 0; o >>= 1)
            mm = fmaxf(mm, __shfl_xor_sync(0xFFFFFFFFu, mm, o));
        if (lid == 0) g_part[blockIdx.x] = mm;
    }
}

// ============================================================================
// Kernel 2: quantize f32 -> e4m3 (RNE satfinite); block first reduces the
// partial maxes itself (scales folded in). Exactly 4 unrolled iterations.
// ============================================================================
__global__ void quant_both_kernel(const float* __restrict__ x, unsigned char* __restrict__ xq,
                                  const float* __restrict__ w, unsigned char* __restrict__ wq) {
    // --- fold-in: reduce g_part -> scales (every block, deterministic) ---
    __shared__ float sred[8];
    __shared__ float s_scales[2];
    {
        int tid = threadIdx.x;
        float mx = 0.0f, mw = 0.0f;
        for (int i = tid; i < XBLK; i += 256) mx = fmaxf(mx, g_part[i]);
        for (int i = XBLK + tid; i < XBLK + WBLK; i += 256) mw = fmaxf(mw, g_part[i]);
        #pragma unroll
        for (int o = 16; o > 0; o >>= 1) {
            mx = fmaxf(mx, __shfl_xor_sync(0xFFFFFFFFu, mx, o));
            mw = fmaxf(mw, __shfl_xor_sync(0xFFFFFFFFu, mw, o));
        }
        int wid = tid >> 5, lid = tid & 31;
        if (lid == 0) sred[wid] = mx;
        __syncthreads();
        if (wid == 0) {
            float a = (lid < 8) ? sred[lid] : 0.0f;
            #pragma unroll
            for (int o = 4; o > 0; o >>= 1) a = fmaxf(a, __shfl_xor_sync(0xFFFFFFFFu, a, o));
            if (lid == 0) s_scales[0] = fmaxf(__fdiv_rn(a, 448.0f), 1e-12f);
        }
        __syncthreads();
        if (lid == 0) sred[wid] = mw;
        __syncthreads();
        if (wid == 0) {
            float a = (lid < 8) ? sred[lid] : 0.0f;
            #pragma unroll
            for (int o = 4; o > 0; o >>= 1) a = fmaxf(a, __shfl_xor_sync(0xFFFFFFFFu, a, o));
            if (lid == 0) {
                s_scales[1] = fmaxf(__fdiv_rn(a, 448.0f), 1e-12f);
                if (blockIdx.x == 0)
                    g_scale_comb = s_scales[0] * s_scales[1];
            }
        }
        __syncthreads();
    }

    bool is_x = (blockIdx.x < QXB);
    const float4* p = reinterpret_cast<const float4*>(is_x ? x : w);
    uint2* q  = reinterpret_cast<uint2*>(is_x ? xq : wq);
    int bid   = is_x ? blockIdx.x : (blockIdx.x - QXB);
    int nblk  = is_x ? QXB : QWB;
    float s   = s_scales[is_x ? 0 : 1];

    size_t i = (size_t)bid * 256 + threadIdx.x;
    size_t stride = (size_t)nblk * 256;
    #pragma unroll
    for (int j = 0; j < 4; j++) {
        size_t idx = i + (size_t)j * stride;
        float4 v0 = p[2 * idx];
        float4 v1 = p[2 * idx + 1];
        float2 f0 = make_float2(__fdiv_rn(v0.x, s), __fdiv_rn(v0.y, s));
        float2 f1 = make_float2(__fdiv_rn(v0.z, s), __fdiv_rn(v0.w, s));
        float2 f2 = make_float2(__fdiv_rn(v1.x, s), __fdiv_rn(v1.y, s));
        float2 f3 = make_float2(__fdiv_rn(v1.z, s), __fdiv_rn(v1.w, s));
        uint32_t b0 = __nv_cvt_float2_to_fp8x2(f0, __NV_SATFINITE, __NV_E4M3);
        uint32_t b1 = __nv_cvt_float2_to_fp8x2(f1, __NV_SATFINITE, __NV_E4M3);
        uint32_t b2 = __nv_cvt_float2_to_fp8x2(f2, __NV_SATFINITE, __NV_E4M3);
        uint32_t b3 = __nv_cvt_float2_to_fp8x2(f3, __NV_SATFINITE, __NV_E4M3);
        uint2 r;
        r.x = (b0 & 0xFFFFu) | (b1 << 16);
        r.y = (b2 & 0xFFFFu) | (b3 << 16);
        q[idx] = r;
    }
}

// ============================================================================
// Kernel 3: FP8 GEMM via mma.sync.m16n8k32 e4m3 — R9 configuration verbatim
// (measured best: 197.5us). CTA 128x128, 256 thr, warp tile 64x32, BK=128,
// 3-stage cp.async, one barrier/iter, immediate offsets, 2 CTA/SM.
// ============================================================================
static constexpr int BM = 128, BN = 128, BK = 128;
static constexpr int STAGES = 3;
static constexpr int PITCH = 144;                   // 128 data + 16 pad
static constexpr int TILE_A = BM * PITCH;           // 18432 bytes
static constexpr int STAGE_B = 2 * TILE_A;          // 36864 bytes per stage
static constexpr int GEMM_SMEM = STAGES * STAGE_B;  // 110592 bytes
static constexpr int KITERS = K_DIM / BK;           // 16
static constexpr int MF_STEP = 16 * PITCH;          // 2304

// one k32 step: 4 A-LDSM + 2 B-LDSM + 16 MMA, all offsets immediate
template <int KS>
__device__ __forceinline__ void kstep(uint32_t aB, uint32_t bB, float (&c)[4][4][4]) {
    uint32_t a[4][4];
    LDMATRIX_X4_OFF(a[0][0], a[0][1], a[0][2], a[0][3], aB, 0 * MF_STEP + KS * 32);
    LDMATRIX_X4_OFF(a[1][0], a[1][1], a[1][2], a[1][3], aB, 1 * MF_STEP + KS * 32);
    LDMATRIX_X4_OFF(a[2][0], a[2][1], a[2][2], a[2][3], aB, 2 * MF_STEP + KS * 32);
    LDMATRIX_X4_OFF(a[3][0], a[3][1], a[3][2], a[3][3], aB, 3 * MF_STEP + KS * 32);

    uint32_t b[4][2];
    {
        uint32_t r0, r1, r2, r3;
        LDMATRIX_X4_OFF(r0, r1, r2, r3, bB, 0 * MF_STEP + KS * 32);
        b[0][0] = r0; b[0][1] = r2;
        b[1][0] = r1; b[1][1] = r3;
        LDMATRIX_X4_OFF(r0, r1, r2, r3, bB, 1 * MF_STEP + KS * 32);
        b[2][0] = r0; b[2][1] = r2;
        b[3][0] = r1; b[3][1] = r3;
    }

    #pragma unroll
    for (int mf = 0; mf < 4; mf++)
        #pragma unroll
        for (int nf = 0; nf < 4; nf++)
            MMA_E4M3(c[mf][nf][0], c[mf][nf][1], c[mf][nf][2], c[mf][nf][3],
                     a[mf][0], a[mf][1], a[mf][2], a[mf][3],
                     b[nf][0], b[nf][1]);
}

// 8 cp.async chunks per thread per stage; offsets immediate
__device__ __forceinline__ void load_stage(uint32_t d0, const uint8_t* sA, const uint8_t* sB) {
    CP_ASYNC16_OFF(d0, 0 * 4608,          sA, 0 * 32 * K_DIM);
    CP_ASYNC16_OFF(d0, 1 * 4608,          sA, 1 * 32 * K_DIM);
    CP_ASYNC16_OFF(d0, 2 * 4608,          sA, 2 * 32 * K_DIM);
    CP_ASYNC16_OFF(d0, 3 * 4608,          sA, 3 * 32 * K_DIM);
    CP_ASYNC16_OFF(d0, TILE_A + 0 * 4608, sB, 0 * 32 * K_DIM);
    CP_ASYNC16_OFF(d0, TILE_A + 1 * 4608, sB, 1 * 32 * K_DIM);
    CP_ASYNC16_OFF(d0, TILE_A + 2 * 4608, sB, 2 * 32 * K_DIM);
    CP_ASYNC16_OFF(d0, TILE_A + 3 * 4608, sB, 3 * 32 * K_DIM);
}

__global__ void __launch_bounds__(256, 2) gemm_kernel(
    const uint8_t* __restrict__ Aq, const uint8_t* __restrict__ Bq,
    float* __restrict__ out)
{
    extern __shared__ char smem[];
    uint32_t sbase = smem_to_u32(smem);
    int tid  = threadIdx.x;
    int lane = tid & 31;
    int wid  = tid >> 5;
    int warp_m = wid & 1;
    int warp_n = wid >> 1;
    int m0 = blockIdx.x * BM;
    int n0 = blockIdx.y * BN;

    int lrow = tid >> 3;
    int lch  = (tid & 7) * 16;
    const uint8_t* srcA = Aq + (size_t)(m0 + lrow) * K_DIM + lch;
    const uint8_t* srcB = Bq + (size_t)(n0 + lrow) * K_DIM + lch;
    uint32_t dof0 = (uint32_t)lrow * PITCH + lch;

    float c[4][4][4];
    #pragma unroll
    for (int mf = 0; mf < 4; mf++)
        #pragma unroll
        for (int nf = 0; nf < 4; nf++)
            #pragma unroll
            for (int e = 0; e < 4; e++) c[mf][nf][e] = 0.0f;

    load_stage(sbase + 0 * STAGE_B + dof0, srcA, srcB); srcA += BK; srcB += BK;
    CP_ASYNC_COMMIT();
    load_stage(sbase + 1 * STAGE_B + dof0, srcA, srcB); srcA += BK; srcB += BK;
    CP_ASYNC_COMMIT();

    int frow = lane & 15;
    int fch  = lane >> 4;
    uint32_t arow = (uint32_t)(warp_m * 64 + frow) * PITCH + fch * 16;
    uint32_t brow = TILE_A + (uint32_t)(warp_n * 32 + frow) * PITCH + fch * 16;

    uint32_t pf_off = 2 * STAGE_B;
    uint32_t cs_off = 0;

    for (int ki = 0; ki < KITERS; ki++) {
        CP_ASYNC_WAIT1();
        __syncthreads();   // stage (ki-1)%3 fully consumed by all warps

        if (ki + 2 < KITERS) {
            load_stage(sbase + pf_off + dof0, srcA, srcB);
            srcA += BK; srcB += BK;
        }
        CP_ASYNC_COMMIT();
        pf_off += STAGE_B; if (pf_off == GEMM_SMEM) pf_off = 0;

        uint32_t aB = sbase + cs_off + arow;
        uint32_t bB = sbase + cs_off + brow;
        cs_off += STAGE_B; if (cs_off == GEMM_SMEM) cs_off = 0;

        kstep<0>(aB, bB, c);   // k bytes 0-31
        kstep<1>(aB, bB, c);   // 32-63
        kstep<2>(aB, bB, c);   // 64-95
        kstep<3>(aB, bB, c);   // 96-127
    }

    // epilogue: scale, round to bf16 (reference casts to bf16), store as f32
    float sc = g_scale_comb;
    int r  = lane >> 2;
    int cq = (lane & 3) * 2;
    #pragma unroll
    for (int mf = 0; mf < 4; mf++) {
        #pragma unroll
        for (int nf = 0; nf < 4; nf++) {
            int gm = m0 + warp_m * 64 + mf * 16 + r;
            int gn = n0 + warp_n * 32 + nf * 8 + cq;
            float2 e0, e1;
            e0.x = __bfloat162float(__float2bfloat16_rn(c[mf][nf][0] * sc));
            e0.y = __bfloat162float(__float2bfloat16_rn(c[mf][nf][1] * sc));
            e1.x = __bfloat162float(__float2bfloat16_rn(c[mf][nf][2] * sc));
            e1.y = __bfloat162float(__float2bfloat16_rn(c[mf][nf][3] * sc));
            *reinterpret_cast<float2*>(out + (size_t)gm * N_DIM + gn) = e0;
            *reinterpret_cast<float2*>(out + (size_t)(gm + 8) * N_DIM + gn) = e1;
        }
    }
}

// ============================================================================
// Host launcher — exactly 3 launches (amax, quant+scales, gemm)
// ============================================================================
extern "C" void kernel_launch(void* const* d_in, const int* in_sizes, int n_in,
                              void* d_out, int out_size) {
    int ix = 0, iw = 1;
    if (n_in >= 2 && in_sizes[1] > in_sizes[0]) { ix = 1; iw = 0; }
    const float* x = (const float*)d_in[ix];
    const float* w = (const float*)d_in[iw];
    float* out = (float*)d_out;

    size_t nx = (size_t)in_sizes[ix];   // 16,777,216
    int M = (int)(nx / K_DIM);          // 8192

    void *xq = nullptr, *wq = nullptr;
    cudaGetSymbolAddress(&xq, g_x_fp8);
    cudaGetSymbolAddress(&wq, g_w_fp8);

    amax_both_kernel<<<XBLK + WBLK, 256>>>(x, w);
    quant_both_kernel<<<QXB + QWB, 256>>>(x, (unsigned char*)xq,
                                          w, (unsigned char*)wq);

    cudaFuncSetAttribute(gemm_kernel, cudaFuncAttributeMaxDynamicSharedMemorySize, GEMM_SMEM);
    dim3 grid(M / BM, N_DIM / BN);
    gemm_kernel<<<grid, 256, GEMM_SMEM>>>((const uint8_t*)xq, (const uint8_t*)wq, out);
}

// round 15
// speedup vs baseline: 1.6053x; 1.1451x over previous
#include <cuda_runtime.h>
#include <cuda_bf16.h>
#include <cuda_fp8.h>
#include <cstdint>

// ============================================================================
// Problem constants — inputs and output are FLOAT32 buffers (bf16 values
// materialized as f32 by the harness; output compared as f32 of bf16 values)
// ============================================================================
static constexpr int K_DIM = 2048;
static constexpr int N_DIM = 2048;
static constexpr int M_MAX = 8192;

// amax: exact-shape, 8 float4 per thread, no loop
static constexpr int XBLK = 2048;
static constexpr int WBLK = 512;
// quant: 4 unrolled iterations of 8 elements per thread
static constexpr int QXB  = 2048;
static constexpr int QWB  = 512;

// fp8 scratch + scalars (device globals — no allocation allowed)
__device__ __align__(128) unsigned char g_x_fp8[(size_t)M_MAX * K_DIM];  // 16 MB
__device__ __align__(128) unsigned char g_w_fp8[(size_t)N_DIM * K_DIM]; //  4 MB
__device__ float g_part[XBLK + WBLK];
__device__ float g_scale_comb;

__device__ __forceinline__ uint32_t smem_to_u32(const void* smem_ptr) {
    uint32_t addr;
    asm("{ .reg .u64 tmp; cvta.to.shared.u64 tmp, %1; cvt.u32.u64 %0, tmp; }"
        : "=r"(addr) : "l"(smem_ptr));
    return addr;
}

#define CP_ASYNC16_OFF(dst, dimm, src, simm) \
    asm volatile("cp.async.cg.shared.global [%0+%1], [%2+%3], 16;" \
                 :: "r"(dst), "n"(dimm), "l"(src), "n"(simm) : "memory")
#define CP_ASYNC_COMMIT() asm volatile("cp.async.commit_group;" ::: "memory")
#define CP_ASYNC_WAIT1()  asm volatile("cp.async.wait_group 1;" ::: "memory")

#define LDMATRIX_X4_OFF(r0, r1, r2, r3, addr, imm) \
    asm volatile("ldmatrix.sync.aligned.m8n8.x4.shared.b16 {%0,%1,%2,%3}, [%4+%5];" \
                 : "=r"(r0), "=r"(r1), "=r"(r2), "=r"(r3) : "r"(addr), "n"(imm))

// split a 4x e4m3 register into two f16x2 registers (exact conversion)
#define FP8X4_TO_F16X2(lo, hi, src) \
    asm("{\n\t.reg .b16 l, h;\n\t" \
        "mov.b32 {l, h}, %2;\n\t" \
        "cvt.rn.f16x2.e4m3x2 %0, l;\n\t" \
        "cvt.rn.f16x2.e4m3x2 %1, h;\n\t}" \
        : "=r"(lo), "=r"(hi) : "r"(src))

#define MMA_F16(c0, c1, c2, c3, a0, a1, a2, a3, b0, b1) \
    asm volatile("mma.sync.aligned.m16n8k16.row.col.f32.f16.f16.f32 " \
                 "{%0,%1,%2,%3}, {%4,%5,%6,%7}, {%8,%9}, {%0,%1,%2,%3};" \
                 : "+f"(c0), "+f"(c1), "+f"(c2), "+f"(c3) \
                 : "r"(a0), "r"(a1), "r"(a2), "r"(a3), "r"(b0), "r"(b1))

// ============================================================================
// Kernel 1: amax -> per-block partials. 8 independent float4 loads (MLP=8).
// ============================================================================
__global__ void amax_both_kernel(const float* __restrict__ x,
                                 const float* __restrict__ w) {
    bool is_x = (blockIdx.x < XBLK);
    const float4* p = reinterpret_cast<const float4*>(is_x ? x : w);
    int bid = is_x ? blockIdx.x : (blockIdx.x - XBLK);

    size_t base = (size_t)bid * (8 * 256) + threadIdx.x;
    float4 v[8];
    #pragma unroll
    for (int j = 0; j < 8; j++) v[j] = p[base + (size_t)j * 256];

    float m[8];
    #pragma unroll
    for (int j = 0; j < 8; j++)
        m[j] = fmaxf(fmaxf(fabsf(v[j].x), fabsf(v[j].y)),
                     fmaxf(fabsf(v[j].z), fabsf(v[j].w)));
    float mm = fmaxf(fmaxf(fmaxf(m[0], m[1]), fmaxf(m[2], m[3])),
                     fmaxf(fmaxf(m[4], m[5]), fmaxf(m[6], m[7])));

    #pragma unroll
    for (int o = 16; o > 0; o >>= 1)
        mm = fmaxf(mm, __shfl_xor_sync(0xFFFFFFFFu, mm, o));
    __shared__ float smax[8];
    int wid = threadIdx.x >> 5, lid = threadIdx.x & 31;
    if (lid == 0) smax[wid] = mm;
    __syncthreads();
    if (wid == 0) {
        mm = (lid < 8) ? smax[lid] : 0.0f;
        #pragma unroll
        for (int o = 4; o > 0; o >>= 1)
            mm = fmaxf(mm, __shfl_xor_sync(0xFFFFFFFFu, mm, o));
        if (lid == 0) g_part[blockIdx.x] = mm;
    }
}

// ============================================================================
// Kernel 2: quantize f32 -> e4m3 (RNE satfinite); block first reduces the
// partial maxes itself (scales folded in). Exactly 4 unrolled iterations.
// ============================================================================
__global__ void quant_both_kernel(const float* __restrict__ x, unsigned char* __restrict__ xq,
                                  const float* __restrict__ w, unsigned char* __restrict__ wq) {
    __shared__ float sred[8];
    __shared__ float s_scales[2];
    {
        int tid = threadIdx.x;
        float mx = 0.0f, mw = 0.0f;
        for (int i = tid; i < XBLK; i += 256) mx = fmaxf(mx, g_part[i]);
        for (int i = XBLK + tid; i < XBLK + WBLK; i += 256) mw = fmaxf(mw, g_part[i]);
        #pragma unroll
        for (int o = 16; o > 0; o >>= 1) {
            mx = fmaxf(mx, __shfl_xor_sync(0xFFFFFFFFu, mx, o));
            mw = fmaxf(mw, __shfl_xor_sync(0xFFFFFFFFu, mw, o));
        }
        int wid = tid >> 5, lid = tid & 31;
        if (lid == 0) sred[wid] = mx;
        __syncthreads();
        if (wid == 0) {
            float a = (lid < 8) ? sred[lid] : 0.0f;
            #pragma unroll
            for (int o = 4; o > 0; o >>= 1) a = fmaxf(a, __shfl_xor_sync(0xFFFFFFFFu, a, o));
            if (lid == 0) s_scales[0] = fmaxf(__fdiv_rn(a, 448.0f), 1e-12f);
        }
        __syncthreads();
        if (lid == 0) sred[wid] = mw;
        __syncthreads();
        if (wid == 0) {
            float a = (lid < 8) ? sred[lid] : 0.0f;
            #pragma unroll
            for (int o = 4; o > 0; o >>= 1) a = fmaxf(a, __shfl_xor_sync(0xFFFFFFFFu, a, o));
            if (lid == 0) {
                s_scales[1] = fmaxf(__fdiv_rn(a, 448.0f), 1e-12f);
                if (blockIdx.x == 0)
                    g_scale_comb = s_scales[0] * s_scales[1];
            }
        }
        __syncthreads();
    }

    bool is_x = (blockIdx.x < QXB);
    const float4* p = reinterpret_cast<const float4*>(is_x ? x : w);
    uint2* q  = reinterpret_cast<uint2*>(is_x ? xq : wq);
    int bid   = is_x ? blockIdx.x : (blockIdx.x - QXB);
    int nblk  = is_x ? QXB : QWB;
    float s   = s_scales[is_x ? 0 : 1];

    size_t i = (size_t)bid * 256 + threadIdx.x;
    size_t stride = (size_t)nblk * 256;
    #pragma unroll
    for (int j = 0; j < 4; j++) {
        size_t idx = i + (size_t)j * stride;
        float4 v0 = p[2 * idx];
        float4 v1 = p[2 * idx + 1];
        float2 f0 = make_float2(__fdiv_rn(v0.x, s), __fdiv_rn(v0.y, s));
        float2 f1 = make_float2(__fdiv_rn(v0.z, s), __fdiv_rn(v0.w, s));
        float2 f2 = make_float2(__fdiv_rn(v1.x, s), __fdiv_rn(v1.y, s));
        float2 f3 = make_float2(__fdiv_rn(v1.z, s), __fdiv_rn(v1.w, s));
        uint32_t b0 = __nv_cvt_float2_to_fp8x2(f0, __NV_SATFINITE, __NV_E4M3);
        uint32_t b1 = __nv_cvt_float2_to_fp8x2(f1, __NV_SATFINITE, __NV_E4M3);
        uint32_t b2 = __nv_cvt_float2_to_fp8x2(f2, __NV_SATFINITE, __NV_E4M3);
        uint32_t b3 = __nv_cvt_float2_to_fp8x2(f3, __NV_SATFINITE, __NV_E4M3);
        uint2 r;
        r.x = (b0 & 0xFFFFu) | (b1 << 16);
        r.y = (b2 & 0xFFFFu) | (b3 << 16);
        q[idx] = r;
    }
}

// ============================================================================
// Kernel 3: GEMM — fp8 in SMEM (low crossbar traffic), explicit one-time
// fragment conversion fp8->f16, native HMMA m16n8k16. R9 skeleton otherwise:
// CTA 128x128, 256 thr, warp tile 64x32, BK=128, 3-stage cp.async, 2 CTA/SM.
// k-permutation from lo/hi split is applied identically to A and B -> exact.
// ============================================================================
static constexpr int BM = 128, BN = 128, BK = 128;
static constexpr int STAGES = 3;
static constexpr int PITCH = 144;                   // 128 data + 16 pad
static constexpr int TILE_A = BM * PITCH;           // 18432 bytes
static constexpr int STAGE_B = 2 * TILE_A;          // 36864 bytes per stage
static constexpr int GEMM_SMEM = STAGES * STAGE_B;  // 110592 bytes
static constexpr int KITERS = K_DIM / BK;           // 16
static constexpr int MF_STEP = 16 * PITCH;          // 2304

// one k32 step: 4 A-LDSM + 2 B-LDSM, convert once per fragment, 32 HMMA
template <int KS>
__device__ __forceinline__ void kstep(uint32_t aB, uint32_t bB, float (&c)[4][4][4]) {
    uint32_t a8[4][4];
    LDMATRIX_X4_OFF(a8[0][0], a8[0][1], a8[0][2], a8[0][3], aB, 0 * MF_STEP + KS * 32);
    LDMATRIX_X4_OFF(a8[1][0], a8[1][1], a8[1][2], a8[1][3], aB, 1 * MF_STEP + KS * 32);
    LDMATRIX_X4_OFF(a8[2][0], a8[2][1], a8[2][2], a8[2][3], aB, 2 * MF_STEP + KS * 32);
    LDMATRIX_X4_OFF(a8[3][0], a8[3][1], a8[3][2], a8[3][3], aB, 3 * MF_STEP + KS * 32);

    uint32_t b8[4][2];
    {
        uint32_t r0, r1, r2, r3;
        LDMATRIX_X4_OFF(r0, r1, r2, r3, bB, 0 * MF_STEP + KS * 32);
        b8[0][0] = r0; b8[0][1] = r2;
        b8[1][0] = r1; b8[1][1] = r3;
        LDMATRIX_X4_OFF(r0, r1, r2, r3, bB, 1 * MF_STEP + KS * 32);
        b8[2][0] = r0; b8[2][1] = r2;
        b8[3][0] = r1; b8[3][1] = r3;
    }

    // convert B once (16 f16 regs), then A per-mf (8 f16 regs live)
    uint32_t bL[4][2], bH[4][2];
    #pragma unroll
    for (int nf = 0; nf < 4; nf++) {
        FP8X4_TO_F16X2(bL[nf][0], bH[nf][0], b8[nf][0]);
        FP8X4_TO_F16X2(bL[nf][1], bH[nf][1], b8[nf][1]);
    }

    #pragma unroll
    for (int mf = 0; mf < 4; mf++) {
        uint32_t aL[4], aH[4];
        #pragma unroll
        for (int e = 0; e < 4; e++)
            FP8X4_TO_F16X2(aL[e], aH[e], a8[mf][e]);
        #pragma unroll
        for (int nf = 0; nf < 4; nf++) {
            MMA_F16(c[mf][nf][0], c[mf][nf][1], c[mf][nf][2], c[mf][nf][3],
                    aL[0], aL[1], aL[2], aL[3], bL[nf][0], bL[nf][1]);
            MMA_F16(c[mf][nf][0], c[mf][nf][1], c[mf][nf][2], c[mf][nf][3],
                    aH[0], aH[1], aH[2], aH[3], bH[nf][0], bH[nf][1]);
        }
    }
}

// 8 cp.async chunks per thread per stage; offsets immediate
__device__ __forceinline__ void load_stage(uint32_t d0, const uint8_t* sA, const uint8_t* sB) {
    CP_ASYNC16_OFF(d0, 0 * 4608,          sA, 0 * 32 * K_DIM);
    CP_ASYNC16_OFF(d0, 1 * 4608,          sA, 1 * 32 * K_DIM);
    CP_ASYNC16_OFF(d0, 2 * 4608,          sA, 2 * 32 * K_DIM);
    CP_ASYNC16_OFF(d0, 3 * 4608,          sA, 3 * 32 * K_DIM);
    CP_ASYNC16_OFF(d0, TILE_A + 0 * 4608, sB, 0 * 32 * K_DIM);
    CP_ASYNC16_OFF(d0, TILE_A + 1 * 4608, sB, 1 * 32 * K_DIM);
    CP_ASYNC16_OFF(d0, TILE_A + 2 * 4608, sB, 2 * 32 * K_DIM);
    CP_ASYNC16_OFF(d0, TILE_A + 3 * 4608, sB, 3 * 32 * K_DIM);
}

__global__ void __launch_bounds__(256, 2) gemm_kernel(
    const uint8_t* __restrict__ Aq, const uint8_t* __restrict__ Bq,
    float* __restrict__ out)
{
    extern __shared__ char smem[];
    uint32_t sbase = smem_to_u32(smem);
    int tid  = threadIdx.x;
    int lane = tid & 31;
    int wid  = tid >> 5;
    int warp_m = wid & 1;
    int warp_n = wid >> 1;
    int m0 = blockIdx.x * BM;
    int n0 = blockIdx.y * BN;

    int lrow = tid >> 3;
    int lch  = (tid & 7) * 16;
    const uint8_t* srcA = Aq + (size_t)(m0 + lrow) * K_DIM + lch;
    const uint8_t* srcB = Bq + (size_t)(n0 + lrow) * K_DIM + lch;
    uint32_t dof0 = (uint32_t)lrow * PITCH + lch;

    float c[4][4][4];
    #pragma unroll
    for (int mf = 0; mf < 4; mf++)
        #pragma unroll
        for (int nf = 0; nf < 4; nf++)
            #pragma unroll
            for (int e = 0; e < 4; e++) c[mf][nf][e] = 0.0f;

    load_stage(sbase + 0 * STAGE_B + dof0, srcA, srcB); srcA += BK; srcB += BK;
    CP_ASYNC_COMMIT();
    load_stage(sbase + 1 * STAGE_B + dof0, srcA, srcB); srcA += BK; srcB += BK;
    CP_ASYNC_COMMIT();

    int frow = lane & 15;
    int fch  = lane >> 4;
    uint32_t arow = (uint32_t)(warp_m * 64 + frow) * PITCH + fch * 16;
    uint32_t brow = TILE_A + (uint32_t)(warp_n * 32 + frow) * PITCH + fch * 16;

    uint32_t pf_off = 2 * STAGE_B;
    uint32_t cs_off = 0;

    for (int ki = 0; ki < KITERS; ki++) {
        CP_ASYNC_WAIT1();
        __syncthreads();   // stage (ki-1)%3 fully consumed by all warps

        if (ki + 2 < KITERS) {
            load_stage(sbase + pf_off + dof0, srcA, srcB);
            srcA += BK; srcB += BK;
        }
        CP_ASYNC_COMMIT();
        pf_off += STAGE_B; if (pf_off == GEMM_SMEM) pf_off = 0;

        uint32_t aB = sbase + cs_off + arow;
        uint32_t bB = sbase + cs_off + brow;
        cs_off += STAGE_B; if (cs_off == GEMM_SMEM) cs_off = 0;

        kstep<0>(aB, bB, c);   // k bytes 0-31
        kstep<1>(aB, bB, c);   // 32-63
        kstep<2>(aB, bB, c);   // 64-95
        kstep<3>(aB, bB, c);   // 96-127
    }

    // epilogue: scale, round to bf16 (reference casts to bf16), store as f32
    float sc = g_scale_comb;
    int r  = lane >> 2;
    int cq = (lane & 3) * 2;
    #pragma unroll
    for (int mf = 0; mf < 4; mf++) {
        #pragma unroll
        for (int nf = 0; nf < 4; nf++) {
            int gm = m0 + warp_m * 64 + mf * 16 + r;
            int gn = n0 + warp_n * 32 + nf * 8 + cq;
            float2 e0, e1;
            e0.x = __bfloat162float(__float2bfloat16_rn(c[mf][nf][0] * sc));
            e0.y = __bfloat162float(__float2bfloat16_rn(c[mf][nf][1] * sc));
            e1.x = __bfloat162float(__float2bfloat16_rn(c[mf][nf][2] * sc));
            e1.y = __bfloat162float(__float2bfloat16_rn(c[mf][nf][3] * sc));
            *reinterpret_cast<float2*>(out + (size_t)gm * N_DIM + gn) = e0;
            *reinterpret_cast<float2*>(out + (size_t)(gm + 8) * N_DIM + gn) = e1;
        }
    }
}

// ============================================================================
// Host launcher — exactly 3 launches (amax, quant+scales, gemm)
// ============================================================================
extern "C" void kernel_launch(void* const* d_in, const int* in_sizes, int n_in,
                              void* d_out, int out_size) {
    int ix = 0, iw = 1;
    if (n_in >= 2 && in_sizes[1] > in_sizes[0]) { ix = 1; iw = 0; }
    const float* x = (const float*)d_in[ix];
    const float* w = (const float*)d_in[iw];
    float* out = (float*)d_out;

    size_t nx = (size_t)in_sizes[ix];   // 16,777,216
    int M = (int)(nx / K_DIM);          // 8192

    void *xq = nullptr, *wq = nullptr;
    cudaGetSymbolAddress(&xq, g_x_fp8);
    cudaGetSymbolAddress(&wq, g_w_fp8);

    amax_both_kernel<<<XBLK + WBLK, 256>>>(x, w);
    quant_both_kernel<<<QXB + QWB, 256>>>(x, (unsigned char*)xq,
                                          w, (unsigned char*)wq);

    cudaFuncSetAttribute(gemm_kernel, cudaFuncAttributeMaxDynamicSharedMemorySize, GEMM_SMEM);
    dim3 grid(M / BM, N_DIM / BN);
    gemm_kernel<<<grid, 256, GEMM_SMEM>>>((const uint8_t*)xq, (const uint8_t*)wq, out);
}

// round 16
// speedup vs baseline: 1.6421x; 1.0229x over previous
#include <cuda_runtime.h>
#include <cuda_bf16.h>
#include <cuda_fp8.h>
#include <cstdint>

// ============================================================================
// Problem constants — inputs and output are FLOAT32 buffers (bf16 values
// materialized as f32 by the harness; output compared as f32 of bf16 values)
// ============================================================================
static constexpr int K_DIM = 2048;
static constexpr int N_DIM = 2048;
static constexpr int M_MAX = 8192;

// amax: exact-shape, 16 independent float4 per thread, no loop
static constexpr int XBLK = 1024;   // x: 4,194,304 float4 / (1024*256) = 16
static constexpr int WBLK = 256;    // w: 1,048,576 float4 / (256*256)  = 16
// quant: 4 unrolled iterations of 8 elements per thread, loads front-batched
static constexpr int QXB  = 2048;
static constexpr int QWB  = 512;

// fp8 scratch + scalars (device globals — no allocation allowed)
__device__ __align__(128) unsigned char g_x_fp8[(size_t)M_MAX * K_DIM];  // 16 MB
__device__ __align__(128) unsigned char g_w_fp8[(size_t)N_DIM * K_DIM]; //  4 MB
__device__ float g_part[XBLK + WBLK];
__device__ float g_scale_comb;

__device__ __forceinline__ uint32_t smem_to_u32(const void* smem_ptr) {
    uint32_t addr;
    asm("{ .reg .u64 tmp; cvta.to.shared.u64 tmp, %1; cvt.u32.u64 %0, tmp; }"
        : "=r"(addr) : "l"(smem_ptr));
    return addr;
}

#define CP_ASYNC16_OFF(dst, dimm, src, simm) \
    asm volatile("cp.async.cg.shared.global [%0+%1], [%2+%3], 16;" \
                 :: "r"(dst), "n"(dimm), "l"(src), "n"(simm) : "memory")
#define CP_ASYNC_COMMIT() asm volatile("cp.async.commit_group;" ::: "memory")
#define CP_ASYNC_WAIT1()  asm volatile("cp.async.wait_group 1;" ::: "memory")

#define LDMATRIX_X4_OFF(r0, r1, r2, r3, addr, imm) \
    asm volatile("ldmatrix.sync.aligned.m8n8.x4.shared.b16 {%0,%1,%2,%3}, [%4+%5];" \
                 : "=r"(r0), "=r"(r1), "=r"(r2), "=r"(r3) : "r"(addr), "n"(imm))

// split a 4x e4m3 register into two f16x2 registers (exact conversion)
#define FP8X4_TO_F16X2(lo, hi, src) \
    asm("{\n\t.reg .b16 l, h;\n\t" \
        "mov.b32 {l, h}, %2;\n\t" \
        "cvt.rn.f16x2.e4m3x2 %0, l;\n\t" \
        "cvt.rn.f16x2.e4m3x2 %1, h;\n\t}" \
        : "=r"(lo), "=r"(hi) : "r"(src))

#define MMA_F16(c0, c1, c2, c3, a0, a1, a2, a3, b0, b1) \
    asm volatile("mma.sync.aligned.m16n8k16.row.col.f32.f16.f16.f32 " \
                 "{%0,%1,%2,%3}, {%4,%5,%6,%7}, {%8,%9}, {%0,%1,%2,%3};" \
                 : "+f"(c0), "+f"(c1), "+f"(c2), "+f"(c3) \
                 : "r"(a0), "r"(a1), "r"(a2), "r"(a3), "r"(b0), "r"(b1))

// ============================================================================
// Kernel 1: amax -> per-block partials. 16 independent float4 loads (MLP=16).
// ============================================================================
__global__ void amax_both_kernel(const float* __restrict__ x,
                                 const float* __restrict__ w) {
    bool is_x = (blockIdx.x < XBLK);
    const float4* p = reinterpret_cast<const float4*>(is_x ? x : w);
    int bid = is_x ? blockIdx.x : (blockIdx.x - XBLK);

    // block covers 16 * 256 float4, thread t takes [base + j*256]
    size_t base = (size_t)bid * (16 * 256) + threadIdx.x;
    float4 v[16];
    #pragma unroll
    for (int j = 0; j < 16; j++) v[j] = p[base + (size_t)j * 256];

    float m[16];
    #pragma unroll
    for (int j = 0; j < 16; j++)
        m[j] = fmaxf(fmaxf(fabsf(v[j].x), fabsf(v[j].y)),
                     fmaxf(fabsf(v[j].z), fabsf(v[j].w)));
    #pragma unroll
    for (int s = 8; s > 0; s >>= 1)
        #pragma unroll
        for (int j = 0; j < s; j++) m[j] = fmaxf(m[j], m[j + s]);
    float mm = m[0];

    #pragma unroll
    for (int o = 16; o > 0; o >>= 1)
        mm = fmaxf(mm, __shfl_xor_sync(0xFFFFFFFFu, mm, o));
    __shared__ float smax[8];
    int wid = threadIdx.x >> 5, lid = threadIdx.x & 31;
    if (lid == 0) smax[wid] = mm;
    __syncthreads();
    if (wid == 0) {
        mm = (lid < 8) ? smax[lid] : 0.0f;
        #pragma unroll
        for (int o = 4; o > 0; o >>= 1)
            mm = fmaxf(mm, __shfl_xor_sync(0xFFFFFFFFu, mm, o));
        if (lid == 0) g_part[blockIdx.x] = mm;
    }
}

// ============================================================================
// Kernel 2: quantize f32 -> e4m3 (RNE satfinite); block first reduces the
// partial maxes itself (scales folded in). Loads front-batched (MLP=8).
// ============================================================================
__global__ void quant_both_kernel(const float* __restrict__ x, unsigned char* __restrict__ xq,
                                  const float* __restrict__ w, unsigned char* __restrict__ wq) {
    __shared__ float sred[8];
    __shared__ float s_scales[2];
    {
        int tid = threadIdx.x;
        float mx = 0.0f, mw = 0.0f;
        for (int i = tid; i < XBLK; i += 256) mx = fmaxf(mx, g_part[i]);
        for (int i = XBLK + tid; i < XBLK + WBLK; i += 256) mw = fmaxf(mw, g_part[i]);
        #pragma unroll
        for (int o = 16; o > 0; o >>= 1) {
            mx = fmaxf(mx, __shfl_xor_sync(0xFFFFFFFFu, mx, o));
            mw = fmaxf(mw, __shfl_xor_sync(0xFFFFFFFFu, mw, o));
        }
        int wid = tid >> 5, lid = tid & 31;
        if (lid == 0) sred[wid] = mx;
        __syncthreads();
        if (wid == 0) {
            float a = (lid < 8) ? sred[lid] : 0.0f;
            #pragma unroll
            for (int o = 4; o > 0; o >>= 1) a = fmaxf(a, __shfl_xor_sync(0xFFFFFFFFu, a, o));
            if (lid == 0) s_scales[0] = fmaxf(__fdiv_rn(a, 448.0f), 1e-12f);
        }
        __syncthreads();
        if (lid == 0) sred[wid] = mw;
        __syncthreads();
        if (wid == 0) {
            float a = (lid < 8) ? sred[lid] : 0.0f;
            #pragma unroll
            for (int o = 4; o > 0; o >>= 1) a = fmaxf(a, __shfl_xor_sync(0xFFFFFFFFu, a, o));
            if (lid == 0) {
                s_scales[1] = fmaxf(__fdiv_rn(a, 448.0f), 1e-12f);
                if (blockIdx.x == 0)
                    g_scale_comb = s_scales[0] * s_scales[1];
            }
        }
        __syncthreads();
    }

    bool is_x = (blockIdx.x < QXB);
    const float4* p = reinterpret_cast<const float4*>(is_x ? x : w);
    uint2* q  = reinterpret_cast<uint2*>(is_x ? xq : wq);
    int bid   = is_x ? blockIdx.x : (blockIdx.x - QXB);
    int nblk  = is_x ? QXB : QWB;
    float s   = s_scales[is_x ? 0 : 1];

    size_t i = (size_t)bid * 256 + threadIdx.x;
    size_t stride = (size_t)nblk * 256;

    // front-batch all 8 float4 loads (MLP=8), then convert + store
    float4 v[8];
    #pragma unroll
    for (int j = 0; j < 4; j++) {
        size_t idx = i + (size_t)j * stride;
        v[2 * j]     = p[2 * idx];
        v[2 * j + 1] = p[2 * idx + 1];
    }
    #pragma unroll
    for (int j = 0; j < 4; j++) {
        float4 v0 = v[2 * j];
        float4 v1 = v[2 * j + 1];
        float2 f0 = make_float2(__fdiv_rn(v0.x, s), __fdiv_rn(v0.y, s));
        float2 f1 = make_float2(__fdiv_rn(v0.z, s), __fdiv_rn(v0.w, s));
        float2 f2 = make_float2(__fdiv_rn(v1.x, s), __fdiv_rn(v1.y, s));
        float2 f3 = make_float2(__fdiv_rn(v1.z, s), __fdiv_rn(v1.w, s));
        uint32_t b0 = __nv_cvt_float2_to_fp8x2(f0, __NV_SATFINITE, __NV_E4M3);
        uint32_t b1 = __nv_cvt_float2_to_fp8x2(f1, __NV_SATFINITE, __NV_E4M3);
        uint32_t b2 = __nv_cvt_float2_to_fp8x2(f2, __NV_SATFINITE, __NV_E4M3);
        uint32_t b3 = __nv_cvt_float2_to_fp8x2(f3, __NV_SATFINITE, __NV_E4M3);
        uint2 r;
        r.x = (b0 & 0xFFFFu) | (b1 << 16);
        r.y = (b2 & 0xFFFFu) | (b3 << 16);
        q[i + (size_t)j * stride] = r;
    }
}

// ============================================================================
// Kernel 3: GEMM — fp8 in SMEM (low crossbar traffic), one-time fragment
// conversion fp8->f16, native HMMA m16n8k16 (R15 verbatim, measured best).
// CTA 128x128, 256 thr, warp tile 64x32, BK=128, 3-stage cp.async, 2 CTA/SM.
// ============================================================================
static constexpr int BM = 128, BN = 128, BK = 128;
static constexpr int STAGES = 3;
static constexpr int PITCH = 144;                   // 128 data + 16 pad
static constexpr int TILE_A = BM * PITCH;           // 18432 bytes
static constexpr int STAGE_B = 2 * TILE_A;          // 36864 bytes per stage
static constexpr int GEMM_SMEM = STAGES * STAGE_B;  // 110592 bytes
static constexpr int KITERS = K_DIM / BK;           // 16
static constexpr int MF_STEP = 16 * PITCH;          // 2304

template <int KS>
__device__ __forceinline__ void kstep(uint32_t aB, uint32_t bB, float (&c)[4][4][4]) {
    uint32_t a8[4][4];
    LDMATRIX_X4_OFF(a8[0][0], a8[0][1], a8[0][2], a8[0][3], aB, 0 * MF_STEP + KS * 32);
    LDMATRIX_X4_OFF(a8[1][0], a8[1][1], a8[1][2], a8[1][3], aB, 1 * MF_STEP + KS * 32);
    LDMATRIX_X4_OFF(a8[2][0], a8[2][1], a8[2][2], a8[2][3], aB, 2 * MF_STEP + KS * 32);
    LDMATRIX_X4_OFF(a8[3][0], a8[3][1], a8[3][2], a8[3][3], aB, 3 * MF_STEP + KS * 32);

    uint32_t b8[4][2];
    {
        uint32_t r0, r1, r2, r3;
        LDMATRIX_X4_OFF(r0, r1, r2, r3, bB, 0 * MF_STEP + KS * 32);
        b8[0][0] = r0; b8[0][1] = r2;
        b8[1][0] = r1; b8[1][1] = r3;
        LDMATRIX_X4_OFF(r0, r1, r2, r3, bB, 1 * MF_STEP + KS * 32);
        b8[2][0] = r0; b8[2][1] = r2;
        b8[3][0] = r1; b8[3][1] = r3;
    }

    uint32_t bL[4][2], bH[4][2];
    #pragma unroll
    for (int nf = 0; nf < 4; nf++) {
        FP8X4_TO_F16X2(bL[nf][0], bH[nf][0], b8[nf][0]);
        FP8X4_TO_F16X2(bL[nf][1], bH[nf][1], b8[nf][1]);
    }

    #pragma unroll
    for (int mf = 0; mf < 4; mf++) {
        uint32_t aL[4], aH[4];
        #pragma unroll
        for (int e = 0; e < 4; e++)
            FP8X4_TO_F16X2(aL[e], aH[e], a8[mf][e]);
        #pragma unroll
        for (int nf = 0; nf < 4; nf++) {
            MMA_F16(c[mf][nf][0], c[mf][nf][1], c[mf][nf][2], c[mf][nf][3],
                    aL[0], aL[1], aL[2], aL[3], bL[nf][0], bL[nf][1]);
            MMA_F16(c[mf][nf][0], c[mf][nf][1], c[mf][nf][2], c[mf][nf][3],
                    aH[0], aH[1], aH[2], aH[3], bH[nf][0], bH[nf][1]);
        }
    }
}

__device__ __forceinline__ void load_stage(uint32_t d0, const uint8_t* sA, const uint8_t* sB) {
    CP_ASYNC16_OFF(d0, 0 * 4608,          sA, 0 * 32 * K_DIM);
    CP_ASYNC16_OFF(d0, 1 * 4608,          sA, 1 * 32 * K_DIM);
    CP_ASYNC16_OFF(d0, 2 * 4608,          sA, 2 * 32 * K_DIM);
    CP_ASYNC16_OFF(d0, 3 * 4608,          sA, 3 * 32 * K_DIM);
    CP_ASYNC16_OFF(d0, TILE_A + 0 * 4608, sB, 0 * 32 * K_DIM);
    CP_ASYNC16_OFF(d0, TILE_A + 1 * 4608, sB, 1 * 32 * K_DIM);
    CP_ASYNC16_OFF(d0, TILE_A + 2 * 4608, sB, 2 * 32 * K_DIM);
    CP_ASYNC16_OFF(d0, TILE_A + 3 * 4608, sB, 3 * 32 * K_DIM);
}

__global__ void __launch_bounds__(256, 2) gemm_kernel(
    const uint8_t* __restrict__ Aq, const uint8_t* __restrict__ Bq,
    float* __restrict__ out)
{
    extern __shared__ char smem[];
    uint32_t sbase = smem_to_u32(smem);
    int tid  = threadIdx.x;
    int lane = tid & 31;
    int wid  = tid >> 5;
    int warp_m = wid & 1;
    int warp_n = wid >> 1;
    int m0 = blockIdx.x * BM;
    int n0 = blockIdx.y * BN;

    int lrow = tid >> 3;
    int lch  = (tid & 7) * 16;
    const uint8_t* srcA = Aq + (size_t)(m0 + lrow) * K_DIM + lch;
    const uint8_t* srcB = Bq + (size_t)(n0 + lrow) * K_DIM + lch;
    uint32_t dof0 = (uint32_t)lrow * PITCH + lch;

    float c[4][4][4];
    #pragma unroll
    for (int mf = 0; mf < 4; mf++)
        #pragma unroll
        for (int nf = 0; nf < 4; nf++)
            #pragma unroll
            for (int e = 0; e < 4; e++) c[mf][nf][e] = 0.0f;

    load_stage(sbase + 0 * STAGE_B + dof0, srcA, srcB); srcA += BK; srcB += BK;
    CP_ASYNC_COMMIT();
    load_stage(sbase + 1 * STAGE_B + dof0, srcA, srcB); srcA += BK; srcB += BK;
    CP_ASYNC_COMMIT();

    int frow = lane & 15;
    int fch  = lane >> 4;
    uint32_t arow = (uint32_t)(warp_m * 64 + frow) * PITCH + fch * 16;
    uint32_t brow = TILE_A + (uint32_t)(warp_n * 32 + frow) * PITCH + fch * 16;

    uint32_t pf_off = 2 * STAGE_B;
    uint32_t cs_off = 0;

    for (int ki = 0; ki < KITERS; ki++) {
        CP_ASYNC_WAIT1();
        __syncthreads();   // stage (ki-1)%3 fully consumed by all warps

        if (ki + 2 < KITERS) {
            load_stage(sbase + pf_off + dof0, srcA, srcB);
            srcA += BK; srcB += BK;
        }
        CP_ASYNC_COMMIT();
        pf_off += STAGE_B; if (pf_off == GEMM_SMEM) pf_off = 0;

        uint32_t aB = sbase + cs_off + arow;
        uint32_t bB = sbase + cs_off + brow;
        cs_off += STAGE_B; if (cs_off == GEMM_SMEM) cs_off = 0;

        kstep<0>(aB, bB, c);   // k bytes 0-31
        kstep<1>(aB, bB, c);   // 32-63
        kstep<2>(aB, bB, c);   // 64-95
        kstep<3>(aB, bB, c);   // 96-127
    }

    // epilogue: scale, round to bf16 (reference casts to bf16), store as f32
    float sc = g_scale_comb;
    int r  = lane >> 2;
    int cq = (lane & 3) * 2;
    #pragma unroll
    for (int mf = 0; mf < 4; mf++) {
        #pragma unroll
        for (int nf = 0; nf < 4; nf++) {
            int gm = m0 + warp_m * 64 + mf * 16 + r;
            int gn = n0 + warp_n * 32 + nf * 8 + cq;
            float2 e0, e1;
            e0.x = __bfloat162float(__float2bfloat16_rn(c[mf][nf][0] * sc));
            e0.y = __bfloat162float(__float2bfloat16_rn(c[mf][nf][1] * sc));
            e1.x = __bfloat162float(__float2bfloat16_rn(c[mf][nf][2] * sc));
            e1.y = __bfloat162float(__float2bfloat16_rn(c[mf][nf][3] * sc));
            *reinterpret_cast<float2*>(out + (size_t)gm * N_DIM + gn) = e0;
            *reinterpret_cast<float2*>(out + (size_t)(gm + 8) * N_DIM + gn) = e1;
        }
    }
}

// ============================================================================
// Host launcher — exactly 3 launches (amax, quant+scales, gemm)
// ============================================================================
extern "C" void kernel_launch(void* const* d_in, const int* in_sizes, int n_in,
                              void* d_out, int out_size) {
    int ix = 0, iw = 1;
    if (n_in >= 2 && in_sizes[1] > in_sizes[0]) { ix = 1; iw = 0; }
    const float* x = (const float*)d_in[ix];
    const float* w = (const float*)d_in[iw];
    float* out = (float*)d_out;

    size_t nx = (size_t)in_sizes[ix];   // 16,777,216
    int M = (int)(nx / K_DIM);          // 8192

    void *xq = nullptr, *wq = nullptr;
    cudaGetSymbolAddress(&xq, g_x_fp8);
    cudaGetSymbolAddress(&wq, g_w_fp8);

    amax_both_kernel<<<XBLK + WBLK, 256>>>(x, w);
    quant_both_kernel<<<QXB + QWB, 256>>>(x, (unsigned char*)xq,
                                          w, (unsigned char*)wq);

    cudaFuncSetAttribute(gemm_kernel, cudaFuncAttributeMaxDynamicSharedMemorySize, GEMM_SMEM);
    dim3 grid(M / BM, N_DIM / BN);
    gemm_kernel<<<grid, 256, GEMM_SMEM>>>((const uint8_t*)xq, (const uint8_t*)wq, out);
}